// round 12
// baseline (speedup 1.0000x reference)
#include <cuda_runtime.h>
#include <cstdint>

#define BATCH 4
#define NSEQ  1024
#define DDIM  128
#define HDIM  64
#define ROWS  (BATCH*NSEQ)
#define PAD   68   // row stride 272B = 17 x 16B granules (odd) -> conflict-free strided LDS.128

// Scratch (device globals: no allocation allowed)
__device__ float g_U[ROWS*HDIM];
__device__ float g_V[ROWS*HDIM];
__device__ float g_DU[ROWS];
__device__ float g_DV[ROWS];

// tanh(x) = 1 - 2/(exp2(2x/ln2)+1); ex2/rcp.approx abs err ~1e-6 (<< 1e-3 budget)
// arg pre-scaled by caller: computes tanh from e2arg = x * 2/ln2
__device__ __forceinline__ float fast_tanh_pre(float e2arg){
    float e, r;
    asm("ex2.approx.f32 %0, %1;" : "=f"(e) : "f"(e2arg));
    asm("rcp.approx.f32 %0, %1;" : "=f"(r) : "f"(e + 1.0f));
    return fmaf(-2.0f, r, 1.0f);
}

// ---------------------------------------------------------------------------
// Kernel 1: per-row u = emb@Wa, v = emb@Wb + b1, du = w2.u, dv = w2.v
// ---------------------------------------------------------------------------
__global__ __launch_bounds__(128) void k_pre(const float* __restrict__ emb,
                                             const float* __restrict__ W1,
                                             const float* __restrict__ b1,
                                             const float* __restrict__ W2){
    int row0 = blockIdx.x * 8;
    __shared__ float se[8][DDIM];
    __shared__ float sp[8][128];
    int t = threadIdx.x;

    const float4* g4 = (const float4*)(emb + (size_t)row0 * DDIM);
    float4* s4 = (float4*)&se[0][0];
    s4[t]       = g4[t];
    s4[t + 128] = g4[t + 128];
    __syncthreads();

    int h    = t & 63;
    int half = t >> 6;                               // 0 -> u (Wa), 1 -> v (Wb)
    const float* wcol = W1 + half*(DDIM*HDIM) + h;   // W1[(half*128+d)*64 + h]

    float acc[8];
    #pragma unroll
    for (int r = 0; r < 8; r++) acc[r] = 0.f;

    #pragma unroll 8
    for (int d = 0; d < DDIM; d++){
        float w = __ldg(wcol + d*HDIM);
        #pragma unroll
        for (int r = 0; r < 8; r++) acc[r] = fmaf(se[r][d], w, acc[r]);
    }

    float bb  = half ? __ldg(b1 + h) : 0.0f;
    float w2h = __ldg(W2 + h);
    #pragma unroll
    for (int r = 0; r < 8; r++){
        float a = acc[r] + bb;
        if (half) g_V[(row0+r)*HDIM + h] = a;
        else      g_U[(row0+r)*HDIM + h] = a;
        sp[r][t] = a * w2h;
    }
    __syncthreads();

    if (t < 16){
        int r = t >> 1, hf = t & 1;
        float s = 0.f;
        #pragma unroll 8
        for (int k = 0; k < 64; k++) s += sp[r][hf*64 + k];
        if (hf) g_DV[row0+r] = s; else g_DU[row0+r] = s;
    }
}

// ---------------------------------------------------------------------------
// Directed 64x64 block accumulation: acc[a*4+c] += packed sum_h w_h*|u+v|
// u-row = uLane + 16a, v-row = vLane + 16c. U staged in regs; V loaded per-c
// (keeps live registers low -> 3 CTAs/SM).
// ---------------------------------------------------------------------------
__device__ __forceinline__ void pair_block(const float* __restrict__ uB,
                                           const float* __restrict__ vB,
                                           const float* __restrict__ sW,
                                           int uLane, int vLane,
                                           unsigned long long acc[16]){
    const float* pu = uB + uLane*PAD;
    const float* pv = vB + vLane*PAD;

    #pragma unroll 2
    for (int h = 0; h < HDIM; h += 4){
        unsigned long long w0 = *(const unsigned long long*)&sW[h];
        unsigned long long w1 = *(const unsigned long long*)&sW[h+2];
        unsigned long long ua0[4], ua1[4];
        #pragma unroll
        for (int a = 0; a < 4; a++){
            ulonglong2 tt = *(const ulonglong2*)&pu[(16*a)*PAD + h];
            ua0[a] = tt.x; ua1[a] = tt.y;
        }
        #pragma unroll
        for (int c = 0; c < 4; c++){
            ulonglong2 vv = *(const ulonglong2*)&pv[(16*c)*PAD + h];
            #pragma unroll
            for (int a = 0; a < 4; a++){
                unsigned long long t0, t1;
                asm("add.rn.f32x2 %0, %1, %2;" : "=l"(t0) : "l"(ua0[a]), "l"(vv.x));
                t0 &= 0x7fffffff7fffffffULL;           // packed |.| (alu pipe)
                asm("fma.rn.f32x2 %0, %1, %2, %3;"
                    : "=l"(acc[a*4+c]) : "l"(w0), "l"(t0), "l"(acc[a*4+c]));
                asm("add.rn.f32x2 %0, %1, %2;" : "=l"(t1) : "l"(ua1[a]), "l"(vv.y));
                t1 &= 0x7fffffff7fffffffULL;
                asm("fma.rn.f32x2 %0, %1, %2, %3;"
                    : "=l"(acc[a*4+c]) : "l"(w1), "l"(t1), "l"(acc[a*4+c]));
            }
        }
    }
}

// ---------------------------------------------------------------------------
// Kernel 2 (fused pair + symmetrize): one CTA per unordered 64x64 tile pair
// {I,J}. Phase 1 computes tanh scores of block (I,J) -> stashed in smem
// (sVb region, free after phase 1). Phase 2 computes block (J,I);
// val = -0.5*(s1 + s2^T) written for tile (I,J) and transposed for (J,I).
// ---------------------------------------------------------------------------
__global__ __launch_bounds__(256, 3) void k_pairsym(const float* __restrict__ W2,
                                                    const float* __restrict__ b2,
                                                    float* __restrict__ out){
    extern __shared__ float sm[];
    float* sUa  = sm;                  // U rows of tile I
    float* sVa  = sm + 1*64*PAD;       // V rows of tile I
    float* sUb  = sm + 2*64*PAD;       // U rows of tile J
    float* sVb  = sm + 3*64*PAD;       // V rows of tile J
    float* sDUa = sm + 4*64*PAD;
    float* sDVa = sDUa + 64;
    float* sDUb = sDVa + 64;
    float* sDVb = sDUb + 64;
    float* sW   = sDVb + 64;
    float* sS   = sUa;                 // 64x65 transpose staging (reuses sUa)
    float* s1b  = sVb;                 // phase-1 tanh stash (reuses sVb, 16*256 floats)

    int bid  = blockIdx.x;
    int b    = bid / 136;
    int p    = bid % 136;
    int ti = 0;
    while (p >= 16 - ti){ p -= 16 - ti; ti++; }
    int tj = ti + p;                   // 0 <= ti <= tj < 16

    int tid = threadIdx.x;
    int tx = tid & 15, ty = tid >> 4;

    int rI = b*NSEQ + ti*64;
    int rJ = b*NSEQ + tj*64;

    for (int k = tid; k < 64*16; k += 256){
        int r = k >> 4, q = k & 15;
        *(float4*)&sUa[r*PAD + q*4] = *(const float4*)&g_U[(size_t)(rI + r)*HDIM + q*4];
        *(float4*)&sVa[r*PAD + q*4] = *(const float4*)&g_V[(size_t)(rI + r)*HDIM + q*4];
        *(float4*)&sUb[r*PAD + q*4] = *(const float4*)&g_U[(size_t)(rJ + r)*HDIM + q*4];
        *(float4*)&sVb[r*PAD + q*4] = *(const float4*)&g_V[(size_t)(rJ + r)*HDIM + q*4];
    }
    if (tid < 64){
        sDUa[tid] = g_DU[rI + tid];
        sDVa[tid] = g_DV[rI + tid];
        sDUb[tid] = g_DU[rJ + tid];
        sDVb[tid] = g_DV[rJ + tid];
        sW[tid]   = W2[tid];
    }
    __syncthreads();

    const float K2LN = 1.44269504f;           // tanh arg: t * 1/ln2 (t = 2*dot)
    float bb2 = __ldg(b2) * 2.88539008f;      // b2 * 2/ln2

    // ---- phase 1: block (I,J): i = rI + ty + 16a, j = rJ + tx + 16c ----
    {
        unsigned long long acc[16];
        #pragma unroll
        for (int i = 0; i < 16; i++) acc[i] = 0ull;
        pair_block(sUa, sVb, sW, ty, tx, acc);

        // all warps must finish reading sVb before it becomes the s1 stash
        __syncthreads();

        #pragma unroll
        for (int a = 0; a < 4; a++){
            float du = sDUa[ty + 16*a];
            #pragma unroll
            for (int c = 0; c < 4; c++){
                unsigned long long v = acc[a*4+c];
                float lo = __uint_as_float((unsigned int)v);
                float hi = __uint_as_float((unsigned int)(v >> 32));
                float t  = du + sDVb[tx + 16*c] + lo + hi;   // 2*dot
                s1b[(a*4+c)*256 + tid] = fast_tanh_pre(fmaf(t, K2LN, bb2));
            }
        }
    }

    // ---- phase 2: block (J,I): i = rJ + tx + 16a, j = rI + ty + 16c ----
    float val[16];
    {
        unsigned long long acc[16];
        #pragma unroll
        for (int i = 0; i < 16; i++) acc[i] = 0ull;
        pair_block(sUb, sVa, sW, tx, ty, acc);

        #pragma unroll
        for (int a = 0; a < 4; a++){
            float du = sDUb[tx + 16*a];
            #pragma unroll
            for (int c = 0; c < 4; c++){
                unsigned long long v = acc[a*4+c];
                float lo = __uint_as_float((unsigned int)v);
                float hi = __uint_as_float((unsigned int)(v >> 32));
                float t  = du + sDVa[ty + 16*c] + lo + hi;
                float s2 = fast_tanh_pre(fmaf(t, K2LN, bb2));
                // s2 element (a,c) = f(rJ+tx+16a, rI+ty+16c); transpose
                // partner of s1 element (c,a). Final tile-(I,J) value (c,a):
                val[c*4+a] = -0.5f*(s1b[(c*4+a)*256 + tid] + s2);
            }
        }
    }

    // tile (I,J): row rI+ty+16a, col tj*64+tx+16c (coalesced in tx)
    #pragma unroll
    for (int a = 0; a < 4; a++){
        size_t rowoff = (size_t)(b*NSEQ + ti*64 + ty + 16*a)*NSEQ + tj*64;
        #pragma unroll
        for (int c = 0; c < 4; c++)
            out[rowoff + tx + 16*c] = val[a*4+c];
    }

    if (ti != tj){
        // stage transpose in sS (= sUa; safe: all phase-1 reads of sUa are
        // behind the mid-kernel barrier; phase 2 reads only sUb/sVa; s1b=sVb)
        #pragma unroll
        for (int a = 0; a < 4; a++)
            #pragma unroll
            for (int c = 0; c < 4; c++)
                sS[(ty + 16*a)*65 + (tx + 16*c)] = val[a*4+c];
        __syncthreads();
        // tile (J,I): row rJ+ty+16a, col ti*64+tx+16c = sS[col][row]
        #pragma unroll
        for (int a = 0; a < 4; a++){
            size_t rowoff = (size_t)(b*NSEQ + tj*64 + ty + 16*a)*NSEQ + ti*64;
            #pragma unroll
            for (int c = 0; c < 4; c++)
                out[rowoff + tx + 16*c] = sS[(tx + 16*c)*65 + (ty + 16*a)];
        }
    }
}

// ---------------------------------------------------------------------------
extern "C" void kernel_launch(void* const* d_in, const int* in_sizes, int n_in,
                              void* d_out, int out_size){
    const float* emb = (const float*)d_in[0];
    const float* W1  = (const float*)d_in[1];
    const float* b1  = (const float*)d_in[2];
    const float* W2  = (const float*)d_in[3];
    const float* b2  = (const float*)d_in[4];
    float* out = (float*)d_out;

    int smem = (4*64*PAD + 5*64) * (int)sizeof(float);   // 70,912 B
    cudaFuncSetAttribute(k_pairsym,
                         cudaFuncAttributeMaxDynamicSharedMemorySize, smem);

    k_pre    <<<ROWS/8,    128>>>(emb, W1, b1, W2);
    k_pairsym<<<BATCH*136, 256, smem>>>(W2, b2, out);
}

// round 13
// speedup vs baseline: 1.0055x; 1.0055x over previous
#include <cuda_runtime.h>
#include <cstdint>

#define BATCH 4
#define NSEQ  1024
#define DDIM  128
#define HDIM  64
#define ROWS  (BATCH*NSEQ)
#define PAD   68   // row stride 272B = 17 x 16B granules (odd) -> conflict-free strided LDS.128

__device__ float g_U[ROWS*HDIM];
__device__ float g_V[ROWS*HDIM];
__device__ float g_DU[ROWS];
__device__ float g_DV[ROWS];

// tanh from pre-scaled arg e2arg = x * 2/ln2
__device__ __forceinline__ float fast_tanh_pre(float e2arg){
    float e, r;
    asm("ex2.approx.f32 %0, %1;" : "=f"(e) : "f"(e2arg));
    asm("rcp.approx.f32 %0, %1;" : "=f"(r) : "f"(e + 1.0f));
    return fmaf(-2.0f, r, 1.0f);
}

// ---------------------------------------------------------------------------
// Kernel 1: per-row u = emb@Wa, v = emb@Wb + b1, du = w2.u, dv = w2.v
// ---------------------------------------------------------------------------
__global__ __launch_bounds__(128) void k_pre(const float* __restrict__ emb,
                                             const float* __restrict__ W1,
                                             const float* __restrict__ b1,
                                             const float* __restrict__ W2){
    int row0 = blockIdx.x * 8;
    __shared__ float se[8][DDIM];
    __shared__ float sp[8][128];
    int t = threadIdx.x;

    const float4* g4 = (const float4*)(emb + (size_t)row0 * DDIM);
    float4* s4 = (float4*)&se[0][0];
    s4[t]       = g4[t];
    s4[t + 128] = g4[t + 128];
    __syncthreads();

    int h    = t & 63;
    int half = t >> 6;
    const float* wcol = W1 + half*(DDIM*HDIM) + h;

    float acc[8];
    #pragma unroll
    for (int r = 0; r < 8; r++) acc[r] = 0.f;

    #pragma unroll 8
    for (int d = 0; d < DDIM; d++){
        float w = __ldg(wcol + d*HDIM);
        #pragma unroll
        for (int r = 0; r < 8; r++) acc[r] = fmaf(se[r][d], w, acc[r]);
    }

    float bb  = half ? __ldg(b1 + h) : 0.0f;
    float w2h = __ldg(W2 + h);
    #pragma unroll
    for (int r = 0; r < 8; r++){
        float a = acc[r] + bb;
        if (half) g_V[(row0+r)*HDIM + h] = a;
        else      g_U[(row0+r)*HDIM + h] = a;
        sp[r][t] = a * w2h;
    }
    __syncthreads();

    if (t < 16){
        int r = t >> 1, hf = t & 1;
        float s = 0.f;
        #pragma unroll 8
        for (int k = 0; k < 64; k++) s += sp[r][hf*64 + k];
        if (hf) g_DV[row0+r] = s; else g_DU[row0+r] = s;
    }
}

// ---------------------------------------------------------------------------
// Kernel 2: half-pair CTAs. CTA {I,J,half} computes the 32x64 block
//   s1(i,j) = f(i, j),  i in I-half rows, j in J rows
// and the mirrored 64x32 block s2(j,i) = f(j, i), combines
//   val = -0.5*(s1 + s2) (the symmetrized final value), and writes it to
// tile (I,J) rows [half*32..) and (via smem transpose) tile (J,I) cols.
// 256 threads, per-thread 2x4 (phase 1) / 4x2 (phase 2); acc 8 u64 per phase;
// s1 kept in 8 regs. smem 53.2KB -> 4 CTAs/SM; launch_bounds caps regs at 64.
// ---------------------------------------------------------------------------
__global__ __launch_bounds__(256, 4) void k_pairsym(const float* __restrict__ W2,
                                                    const float* __restrict__ b2,
                                                    float* __restrict__ out){
    extern __shared__ float sm[];
    float* sUa  = sm;                    // U rows of I-half  (32)
    float* sVa  = sm + 32*PAD;           // V rows of I-half  (32)
    float* sUb  = sm + 64*PAD;           // U rows of J       (64)
    float* sVb  = sm + 128*PAD;          // V rows of J       (64)
    float* sDUa = sm + 192*PAD;          // du of I-half (32)
    float* sDVa = sDUa + 32;             // dv of I-half (32)
    float* sDUb = sDVa + 32;             // du of J (64)
    float* sDVb = sDUb + 64;             // dv of J (64)
    float* sW   = sDVb + 64;             // W2 (64)
    float* sS   = sUa;                   // 64x33 transpose staging (overlays sUa)

    int bid  = blockIdx.x;
    int half = bid & 1;
    int pp   = bid >> 1;
    int b    = pp / 136;
    int p    = pp % 136;
    int ti = 0;
    while (p >= 16 - ti){ p -= 16 - ti; ti++; }
    int tj = ti + p;                     // 0 <= ti <= tj < 16

    int tid = threadIdx.x;
    int tx = tid & 15, ty = tid >> 4;

    int rIh = b*NSEQ + ti*64 + half*32;  // I-half base row
    int rJ  = b*NSEQ + tj*64;

    // stage I-half (32 rows) and J (64 rows)
    for (int k2 = tid; k2 < 32*16; k2 += 256){
        int r = k2 >> 4, q = k2 & 15;
        *(float4*)&sUa[r*PAD + q*4] = *(const float4*)&g_U[(size_t)(rIh + r)*HDIM + q*4];
        *(float4*)&sVa[r*PAD + q*4] = *(const float4*)&g_V[(size_t)(rIh + r)*HDIM + q*4];
    }
    for (int k2 = tid; k2 < 64*16; k2 += 256){
        int r = k2 >> 4, q = k2 & 15;
        *(float4*)&sUb[r*PAD + q*4] = *(const float4*)&g_U[(size_t)(rJ + r)*HDIM + q*4];
        *(float4*)&sVb[r*PAD + q*4] = *(const float4*)&g_V[(size_t)(rJ + r)*HDIM + q*4];
    }
    if (tid < 64){
        sDUb[tid] = g_DU[rJ + tid];
        sDVb[tid] = g_DV[rJ + tid];
        sW[tid]   = W2[tid];
    }
    if (tid < 32){
        sDUa[tid] = g_DU[rIh + tid];
        sDVa[tid] = g_DV[rIh + tid];
    }
    __syncthreads();

    const float K2LN = 1.44269504f;            // arg scale: t * 1/ln2 (t = 2*dot)
    float bb2 = __ldg(b2) * 2.88539008f;       // b2 * 2/ln2

    // ---- phase 1: s1(i,j), i = rIh + ty + 16a (a<2), j = rJ + tx + 16c (c<4)
    float s1[8];
    {
        unsigned long long acc[8];
        #pragma unroll
        for (int i = 0; i < 8; i++) acc[i] = 0ull;
        const float* pu = sUa + ty*PAD;
        const float* pv = sVb + tx*PAD;
        #pragma unroll 2
        for (int h = 0; h < HDIM; h += 4){
            unsigned long long w0 = *(const unsigned long long*)&sW[h];
            unsigned long long w1 = *(const unsigned long long*)&sW[h+2];
            unsigned long long ua0[2], ua1[2];
            #pragma unroll
            for (int a = 0; a < 2; a++){
                ulonglong2 tt = *(const ulonglong2*)&pu[(16*a)*PAD + h];
                ua0[a] = tt.x; ua1[a] = tt.y;
            }
            #pragma unroll
            for (int c = 0; c < 4; c++){
                ulonglong2 vv = *(const ulonglong2*)&pv[(16*c)*PAD + h];
                #pragma unroll
                for (int a = 0; a < 2; a++){
                    unsigned long long t0, t1;
                    asm("add.rn.f32x2 %0, %1, %2;" : "=l"(t0) : "l"(ua0[a]), "l"(vv.x));
                    t0 &= 0x7fffffff7fffffffULL;
                    asm("fma.rn.f32x2 %0, %1, %2, %3;"
                        : "=l"(acc[a*4+c]) : "l"(w0), "l"(t0), "l"(acc[a*4+c]));
                    asm("add.rn.f32x2 %0, %1, %2;" : "=l"(t1) : "l"(ua1[a]), "l"(vv.y));
                    t1 &= 0x7fffffff7fffffffULL;
                    asm("fma.rn.f32x2 %0, %1, %2, %3;"
                        : "=l"(acc[a*4+c]) : "l"(w1), "l"(t1), "l"(acc[a*4+c]));
                }
            }
        }
        #pragma unroll
        for (int a = 0; a < 2; a++){
            float du = sDUa[ty + 16*a];
            #pragma unroll
            for (int c = 0; c < 4; c++){
                unsigned long long v = acc[a*4+c];
                float lo = __uint_as_float((unsigned int)v);
                float hi = __uint_as_float((unsigned int)(v >> 32));
                float t  = du + sDVb[tx + 16*c] + lo + hi;      // 2*dot
                s1[a*4+c] = fast_tanh_pre(fmaf(t, K2LN, bb2));
            }
        }
    }

    // ---- phase 2: s2(j,i), u-rows j = rJ + tx + 16c (c<4), v i = rIh + ty + 16a
    float val[8];
    {
        unsigned long long acc[8];
        #pragma unroll
        for (int i = 0; i < 8; i++) acc[i] = 0ull;
        const float* pu = sUb + tx*PAD;
        const float* pv = sVa + ty*PAD;
        #pragma unroll 2
        for (int h = 0; h < HDIM; h += 4){
            unsigned long long w0 = *(const unsigned long long*)&sW[h];
            unsigned long long w1 = *(const unsigned long long*)&sW[h+2];
            unsigned long long ub0[4], ub1[4];
            #pragma unroll
            for (int c = 0; c < 4; c++){
                ulonglong2 tt = *(const ulonglong2*)&pu[(16*c)*PAD + h];
                ub0[c] = tt.x; ub1[c] = tt.y;
            }
            #pragma unroll
            for (int a = 0; a < 2; a++){
                ulonglong2 vv = *(const ulonglong2*)&pv[(16*a)*PAD + h];
                #pragma unroll
                for (int c = 0; c < 4; c++){
                    unsigned long long t0, t1;
                    asm("add.rn.f32x2 %0, %1, %2;" : "=l"(t0) : "l"(ub0[c]), "l"(vv.x));
                    t0 &= 0x7fffffff7fffffffULL;
                    asm("fma.rn.f32x2 %0, %1, %2, %3;"
                        : "=l"(acc[c*2+a]) : "l"(w0), "l"(t0), "l"(acc[c*2+a]));
                    asm("add.rn.f32x2 %0, %1, %2;" : "=l"(t1) : "l"(ub1[c]), "l"(vv.y));
                    t1 &= 0x7fffffff7fffffffULL;
                    asm("fma.rn.f32x2 %0, %1, %2, %3;"
                        : "=l"(acc[c*2+a]) : "l"(w1), "l"(t1), "l"(acc[c*2+a]));
                }
            }
        }
        #pragma unroll
        for (int c = 0; c < 4; c++){
            float du = sDUb[tx + 16*c];
            #pragma unroll
            for (int a = 0; a < 2; a++){
                unsigned long long v = acc[c*2+a];
                float lo = __uint_as_float((unsigned int)v);
                float hi = __uint_as_float((unsigned int)(v >> 32));
                float t  = du + sDVa[ty + 16*a] + lo + hi;
                float s2 = fast_tanh_pre(fmaf(t, K2LN, bb2));
                val[a*4+c] = -0.5f*(s1[a*4+c] + s2);
            }
        }
    }

    // write tile (I,J) rows [half*32..): row = rIh-local, col = tj*64+tx+16c
    #pragma unroll
    for (int a = 0; a < 2; a++){
        size_t rowoff = (size_t)(b*NSEQ + ti*64 + half*32 + ty + 16*a)*NSEQ + tj*64;
        #pragma unroll
        for (int c = 0; c < 4; c++)
            out[rowoff + tx + 16*c] = val[a*4+c];
    }

    // transpose write tile (J,I) cols [half*32..): stage val^T in sS[64][33]
    __syncthreads();           // all warps done reading sUa (phase 1 complete)
    #pragma unroll
    for (int a = 0; a < 2; a++)
        #pragma unroll
        for (int c = 0; c < 4; c++)
            sS[(tx + 16*c)*33 + (ty + 16*a)] = val[a*4+c];
    __syncthreads();
    {
        int x = tid & 31, y = tid >> 5;          // 32 cols, 8 row-groups
        #pragma unroll
        for (int r = y; r < 64; r += 8)
            out[(size_t)(b*NSEQ + tj*64 + r)*NSEQ + ti*64 + half*32 + x] = sS[r*33 + x];
    }
}

// ---------------------------------------------------------------------------
extern "C" void kernel_launch(void* const* d_in, const int* in_sizes, int n_in,
                              void* d_out, int out_size){
    const float* emb = (const float*)d_in[0];
    const float* W1  = (const float*)d_in[1];
    const float* b1  = (const float*)d_in[2];
    const float* W2  = (const float*)d_in[3];
    const float* b2  = (const float*)d_in[4];
    float* out = (float*)d_out;

    int smem = (192*PAD + 256) * (int)sizeof(float);   // 53,248 B
    cudaFuncSetAttribute(k_pairsym,
                         cudaFuncAttributeMaxDynamicSharedMemorySize, smem);

    k_pre    <<<ROWS/8,      128>>>(emb, W1, b1, W2);
    k_pairsym<<<BATCH*136*2, 256, smem>>>(W2, b2, out);
}

// round 17
// speedup vs baseline: 1.2600x; 1.2531x over previous
#include <cuda_runtime.h>
#include <cuda_fp16.h>
#include <cstdint>

#define BATCH 4
#define NSEQ  1024
#define DDIM  128
#define HDIM  64
#define ROWS  (BATCH*NSEQ)
#define HPITCH 72   // halves per smem row: 144B = 9 x 16B granules (odd -> conflict-free)

// Scratch (device globals; no allocation allowed)
__device__ __half g_U[ROWS*HDIM];
__device__ __half g_V[ROWS*HDIM];
__device__ float  g_DU[ROWS];
__device__ float  g_DV[ROWS];

__device__ __forceinline__ float fast_tanh_pre(float e2arg){
    float e, r;
    asm("ex2.approx.f32 %0, %1;" : "=f"(e) : "f"(e2arg));
    asm("rcp.approx.f32 %0, %1;" : "=f"(r) : "f"(e + 1.0f));
    return fmaf(-2.0f, r, 1.0f);
}

__device__ __forceinline__ __half2 u2h(unsigned x){ __half2 h; *(unsigned*)&h = x; return h; }
__device__ __forceinline__ unsigned h2u(__half2 h){ return *(unsigned*)&h; }

// ---------------------------------------------------------------------------
// Kernel 1: u = emb@Wa, v = emb@Wb + b1 (stored fp16); du = w2.u, dv = w2.v
// computed in fp32 FROM THE ROUNDED fp16 values (keeps relu identity exact).
// ---------------------------------------------------------------------------
__global__ __launch_bounds__(128) void k_pre(const float* __restrict__ emb,
                                             const float* __restrict__ W1,
                                             const float* __restrict__ b1,
                                             const float* __restrict__ W2){
    int row0 = blockIdx.x * 8;
    __shared__ float se[8][DDIM];
    __shared__ float sp[8][128];
    int t = threadIdx.x;

    const float4* g4 = (const float4*)(emb + (size_t)row0 * DDIM);
    float4* s4 = (float4*)&se[0][0];
    s4[t]       = g4[t];
    s4[t + 128] = g4[t + 128];
    __syncthreads();

    int h    = t & 63;
    int half = t >> 6;
    const float* wcol = W1 + half*(DDIM*HDIM) + h;

    float acc[8];
    #pragma unroll
    for (int r = 0; r < 8; r++) acc[r] = 0.f;

    #pragma unroll 8
    for (int d = 0; d < DDIM; d++){
        float w = __ldg(wcol + d*HDIM);
        #pragma unroll
        for (int r = 0; r < 8; r++) acc[r] = fmaf(se[r][d], w, acc[r]);
    }

    float bb  = half ? __ldg(b1 + h) : 0.0f;
    float w2h = __ldg(W2 + h);
    #pragma unroll
    for (int r = 0; r < 8; r++){
        float a = acc[r] + bb;
        __half ha = __float2half_rn(a);
        if (half) g_V[(row0+r)*HDIM + h] = ha;
        else      g_U[(row0+r)*HDIM + h] = ha;
        sp[r][t] = __half2float(ha) * w2h;     // du/dv from ROUNDED value
    }
    __syncthreads();

    if (t < 16){
        int r = t >> 1, hf = t & 1;
        float s = 0.f;
        #pragma unroll 8
        for (int k = 0; k < 64; k++) s += sp[r][hf*64 + k];
        if (hf) g_DV[row0+r] = s; else g_DU[row0+r] = s;
    }
}

// ---------------------------------------------------------------------------
// Directed 64x64 block in fp16: out[a*4+c] accumulates S = sum_h w_h*|u+v|
// (fp16 HADD2/abs/HFMA2, flushed to fp32 every 16 h), then tanh epilogue.
// u-row = uLane+16a, v-row = vLane+16c within staged fp16 tiles.
// ---------------------------------------------------------------------------
__device__ __forceinline__ void pair_block_h(const __half* __restrict__ uB,
                                             const __half* __restrict__ vB,
                                             const __half2* __restrict__ sW2,
                                             const float* __restrict__ dU,
                                             const float* __restrict__ dV,
                                             int uLane, int vLane,
                                             float bb2, float out16[16]){
    const __half* pu = uB + uLane*HPITCH;
    const __half* pv = vB + vLane*HPITCH;

    __half2 acc2[16];
    float   accf[16];
    #pragma unroll
    for (int i = 0; i < 16; i++){ acc2[i] = u2h(0u); accf[i] = 0.f; }

    #pragma unroll
    for (int chunk = 0; chunk < 8; chunk++){          // 8 h per chunk
        uint4 wq = ((const uint4*)sW2)[chunk];        // 4 x half2 weights
        uint4 ua[4];
        #pragma unroll
        for (int a = 0; a < 4; a++)
            ua[a] = *(const uint4*)(pu + (16*a)*HPITCH + chunk*8);
        #pragma unroll
        for (int c = 0; c < 4; c++){
            uint4 vv = *(const uint4*)(pv + (16*c)*HPITCH + chunk*8);
            #pragma unroll
            for (int a = 0; a < 4; a++){
                unsigned uw[4] = {ua[a].x, ua[a].y, ua[a].z, ua[a].w};
                unsigned vw[4] = {vv.x, vv.y, vv.z, vv.w};
                unsigned ww[4] = {wq.x, wq.y, wq.z, wq.w};
                #pragma unroll
                for (int k = 0; k < 4; k++){
                    __half2 tt = __hadd2(u2h(uw[k]), u2h(vw[k]));
                    unsigned ta = h2u(tt) & 0x7FFF7FFFu;       // packed |.|
                    acc2[a*4+c] = __hfma2(u2h(ww[k]), u2h(ta), acc2[a*4+c]);
                }
            }
        }
        if (chunk & 1){                               // flush every 16 h
            #pragma unroll
            for (int i = 0; i < 16; i++){
                float2 f = __half22float2(acc2[i]);
                accf[i] += f.x + f.y;
                acc2[i] = u2h(0u);
            }
        }
    }

    const float K2LN = 1.44269504f;
    #pragma unroll
    for (int a = 0; a < 4; a++){
        float du = dU[uLane + 16*a];
        #pragma unroll
        for (int c = 0; c < 4; c++){
            float t2 = du + dV[vLane + 16*c] + accf[a*4+c];    // 2*dot
            out16[a*4+c] = fast_tanh_pre(fmaf(t2, K2LN, bb2));
        }
    }
}

// ---------------------------------------------------------------------------
// Kernel 2: one CTA per unordered 64x64 tile pair {I,J}; fp16 tiles.
// ---------------------------------------------------------------------------
__global__ __launch_bounds__(256, 3) void k_pairsym(const float* __restrict__ W2,
                                                    const float* __restrict__ b2,
                                                    float* __restrict__ out){
    extern __shared__ char smraw[];
    __half* sUa = (__half*)smraw;                    // 64*72 halves (9216 B)
    __half* sVa = sUa + 64*HPITCH;
    __half* sUb = sVa + 64*HPITCH;
    __half* sVb = sUb + 64*HPITCH;
    float*  sDUa = (float*)(sVb + 64*HPITCH);        // 36864 B offset, aligned
    float*  sDVa = sDUa + 64;
    float*  sDUb = sDVa + 64;
    float*  sDVb = sDUb + 64;
    __half2* sW2 = (__half2*)(sDVb + 64);            // 32 half2 (offset 37888, 16B-aligned)
    float*  sS  = (float*)smraw;                     // 64x65 fp32 transpose staging (16,640 B)

    int bid  = blockIdx.x;
    int b    = bid / 136;
    int p    = bid % 136;
    int ti = 0;
    while (p >= 16 - ti){ p -= 16 - ti; ti++; }
    int tj = ti + p;                                 // 0 <= ti <= tj < 16

    int tid = threadIdx.x;
    int tx = tid & 15, ty = tid >> 4;

    int rI = b*NSEQ + ti*64;
    int rJ = b*NSEQ + tj*64;

    // stage fp16 tiles: 64 rows x 128 B each, pitch 144 B
    for (int k2 = tid; k2 < 64*8; k2 += 256){
        int r = k2 >> 3, q = k2 & 7;
        *(uint4*)(sUa + r*HPITCH + q*8) = ((const uint4*)g_U)[(size_t)(rI + r)*8 + q];
        *(uint4*)(sVa + r*HPITCH + q*8) = ((const uint4*)g_V)[(size_t)(rI + r)*8 + q];
        *(uint4*)(sUb + r*HPITCH + q*8) = ((const uint4*)g_U)[(size_t)(rJ + r)*8 + q];
        *(uint4*)(sVb + r*HPITCH + q*8) = ((const uint4*)g_V)[(size_t)(rJ + r)*8 + q];
    }
    if (tid < 64){
        sDUa[tid] = g_DU[rI + tid];
        sDVa[tid] = g_DV[rI + tid];
        sDUb[tid] = g_DU[rJ + tid];
        sDVb[tid] = g_DV[rJ + tid];
    }
    if (tid < 32)
        sW2[tid] = __floats2half2_rn(W2[2*tid], W2[2*tid + 1]);
    __syncthreads();

    float bb2 = __ldg(b2) * 2.88539008f;             // b2 * 2/ln2

    // phase 1: s1[a][c] = f(rI+ty+16a, rJ+tx+16c)
    float s1[16];
    pair_block_h(sUa, sVb, sW2, sDUa, sDVb, ty, tx, bb2, s1);
    // phase 2: s2[a][c] = f(rJ+tx+16a, rI+ty+16c); partner of s1[c][a]
    float s2[16];
    pair_block_h(sUb, sVa, sW2, sDUb, sDVa, tx, ty, bb2, s2);

    float val[16];
    #pragma unroll
    for (int a = 0; a < 4; a++)
        #pragma unroll
        for (int c = 0; c < 4; c++)
            val[a*4+c] = -0.5f*(s1[a*4+c] + s2[c*4+a]);

    // tile (I,J): row rI+ty+16a, col tj*64+tx+16c (coalesced in tx)
    #pragma unroll
    for (int a = 0; a < 4; a++){
        size_t rowoff = (size_t)(b*NSEQ + ti*64 + ty + 16*a)*NSEQ + tj*64;
        #pragma unroll
        for (int c = 0; c < 4; c++)
            out[rowoff + tx + 16*c] = val[a*4+c];
    }

    if (ti != tj){
        __syncthreads();     // everyone done with tiles; sS overlays sUa/sVa
        #pragma unroll
        for (int a = 0; a < 4; a++)
            #pragma unroll
            for (int c = 0; c < 4; c++)
                sS[(ty + 16*a)*65 + (tx + 16*c)] = val[a*4+c];
        __syncthreads();
        // tile (J,I): row rJ+ty+16a, col ti*64+tx+16c = sS[col][row]
        #pragma unroll
        for (int a = 0; a < 4; a++){
            size_t rowoff = (size_t)(b*NSEQ + tj*64 + ty + 16*a)*NSEQ + ti*64;
            #pragma unroll
            for (int c = 0; c < 4; c++)
                out[rowoff + tx + 16*c] = sS[(tx + 16*c)*65 + (ty + 16*a)];
        }
    }
}

// ---------------------------------------------------------------------------
extern "C" void kernel_launch(void* const* d_in, const int* in_sizes, int n_in,
                              void* d_out, int out_size){
    const float* emb = (const float*)d_in[0];
    const float* W1  = (const float*)d_in[1];
    const float* b1  = (const float*)d_in[2];
    const float* W2  = (const float*)d_in[3];
    const float* b2  = (const float*)d_in[4];
    float* out = (float*)d_out;

    int smem = 4*64*HPITCH*2 + 4*64*4 + 32*4;        // 38,016 B
    cudaFuncSetAttribute(k_pairsym,
                         cudaFuncAttributeMaxDynamicSharedMemorySize, smem);

    k_pre    <<<ROWS/8,    128>>>(emb, W1, b1, W2);
    k_pairsym<<<BATCH*136, 256, smem>>>(W2, b2, out);
}